// round 2
// baseline (speedup 1.0000x reference)
#include <cuda_runtime.h>

// shift_Windows: reduces to GEMM  Y[m, o] = sum_k A[m, k] * W[o, k] + bias[o]
// m = (b, g, p): b in [0,2), g in [0,2), p in [0,13824)
// k = s*32 + c, gathered from x at t = (g*32 + s + 48) & 63:
//     A[m,k] = x[((b*32 + c)*64 + t)*13824 + p]
// o = s'*32 + c', scattered to out at t' = (g*32 + s' + 48) & 63:
//     out[((b*32 + c')*64 + t')*13824 + p] = Y[m,o]

#define TM 64
#define TN 64
#define KB 16
#define PDIM 13824  // 24^3

__global__ __launch_bounds__(256, 4) void swin_gemm_f32(
    const float* __restrict__ x,
    const float* __restrict__ W,
    const float* __restrict__ bias,
    float* __restrict__ out)
{
    __shared__ float As[KB][TM];        // As[kk][mm], rows contiguous in p
    __shared__ float Bs[KB][TN + 4];    // Bs[kk][oo], padded, 16B-aligned rows
    __shared__ float Cs[TN][TM + 2];    // epilogue staging: Cs[nn][mm]

    const int tid = threadIdx.x;
    const int tx = tid & 15;
    const int ty = tid >> 4;
    const int p0 = blockIdx.x * TM;
    const int o0 = blockIdx.y * TN;
    const int bg = blockIdx.z;
    const int b  = bg >> 1;
    const int g  = bg & 1;

    float acc[4][4] = {};

    for (int k0 = 0; k0 < 1024; k0 += KB) {
        // --- load A tile: As[kk][mm] = x[b, c(k), t(k), p0+mm] ---
        #pragma unroll
        for (int w = 0; w < 4; w++) {
            int e  = tid + w * 256;
            int kk = e >> 6;            // 0..15
            int mm = e & 63;
            int k  = k0 + kk;
            int c  = k & 31;
            int s  = k >> 5;
            int t  = (g * 32 + s + 48) & 63;
            As[kk][mm] = x[((size_t)((b * 32 + c) * 64 + t)) * PDIM + p0 + mm];
        }
        // --- load B tile: Bs[kk][oo] = W[(o0+oo)*1024 + k0+kk] ---
        #pragma unroll
        for (int w = 0; w < 4; w++) {
            int e  = tid + w * 256;
            int kk = e & 15;
            int oo = e >> 4;            // 0..63
            Bs[kk][oo] = W[(size_t)(o0 + oo) * 1024 + (k0 + kk)];
        }
        __syncthreads();

        // --- 64x64x16 FMA, 4x4 per thread, vectorized smem reads ---
        #pragma unroll
        for (int kk = 0; kk < KB; kk++) {
            float4 a4 = *(const float4*)&As[kk][ty * 4];
            float4 b4 = *(const float4*)&Bs[kk][tx * 4];
            float av[4] = {a4.x, a4.y, a4.z, a4.w};
            float bv[4] = {b4.x, b4.y, b4.z, b4.w};
            #pragma unroll
            for (int i = 0; i < 4; i++)
                #pragma unroll
                for (int j = 0; j < 4; j++)
                    acc[i][j] += av[i] * bv[j];
        }
        __syncthreads();
    }

    // --- stage results: Cs[nn][mm] so global writes are contiguous in p ---
    #pragma unroll
    for (int i = 0; i < 4; i++)
        #pragma unroll
        for (int j = 0; j < 4; j++)
            Cs[tx * 4 + j][ty * 4 + i] = acc[i][j];
    __syncthreads();

    // --- scatter epilogue: per output feature o, 64 contiguous p writes ---
    #pragma unroll
    for (int w = 0; w < 16; w++) {
        int e  = tid + w * 256;
        int nn = e >> 6;                // 0..63
        int mm = e & 63;
        int o  = o0 + nn;
        int c  = o & 31;
        int s  = o >> 5;
        int t  = (g * 32 + s + 48) & 63;
        out[((size_t)((b * 32 + c) * 64 + t)) * PDIM + p0 + mm] = Cs[nn][mm] + bias[o];
    }
}

extern "C" void kernel_launch(void* const* d_in, const int* in_sizes, int n_in,
                              void* d_out, int out_size)
{
    const float* x    = (const float*)d_in[0];  // (2, 32, 96, 96, 96) fp32
    const float* W    = (const float*)d_in[1];  // (1024, 1024) fp32
    const float* bias = (const float*)d_in[2];  // (1024,) fp32
    float* out        = (float*)d_out;          // same shape as x

    dim3 grid(PDIM / TM /*216*/, 1024 / TN /*16*/, 4 /* b*2+g */);
    swin_gemm_f32<<<grid, 256>>>(x, W, bias, out);
}

// round 9
// speedup vs baseline: 1.9308x; 1.9308x over previous
#include <cuda_runtime.h>
#include <cuda_bf16.h>
#include <cstdint>

// Y[m,o] = sum_k A[m,k]*W[o,k] + bias[o]
// m=(b,g,p), k=s*32+c gathered from x at t=(g*32+s+48)&63; same map on output o.
// K-chunk of 32 => s == chunk index, one t-plane per chunk.
// Split precision: A=Ah+Al, W=Bh+Bl (bf16). Y ~= Ah*Bh + Al*Bh + Ah*Bl.

#define PDIM 13824
#define NCH  32          // K chunks of 32
// smem layout (bytes, per stage)
#define A_STRIDE 272     // [k=32][m=128] bf16 rows padded 256->272
#define B_STRIDE 80      // [o=128][k=32] bf16 rows padded 64->80
#define OFF_AHI 0
#define OFF_ALO 8704     // 32*272
#define OFF_BHI 17408
#define OFF_BLO 27648    // +128*80
#define STAGE   37888
#define DYN_SMEM (2*STAGE)

__device__ __forceinline__ uint32_t smem_u32(const void* p) {
    uint32_t a;
    asm("{ .reg .u64 t; cvta.to.shared.u64 t, %1; cvt.u32.u64 %0, t; }" : "=r"(a) : "l"(p));
    return a;
}
__device__ __forceinline__ void ldsm_x4_t(uint32_t* r, uint32_t a) {
    asm volatile("ldmatrix.sync.aligned.m8n8.x4.trans.shared.b16 {%0,%1,%2,%3},[%4];"
        : "=r"(r[0]), "=r"(r[1]), "=r"(r[2]), "=r"(r[3]) : "r"(a));
}
__device__ __forceinline__ void ldsm_x4(uint32_t* r, uint32_t a) {
    asm volatile("ldmatrix.sync.aligned.m8n8.x4.shared.b16 {%0,%1,%2,%3},[%4];"
        : "=r"(r[0]), "=r"(r[1]), "=r"(r[2]), "=r"(r[3]) : "r"(a));
}
__device__ __forceinline__ void mma_bf16(float* c, const uint32_t* a, const uint32_t* b) {
    asm volatile("mma.sync.aligned.m16n8k16.row.col.f32.bf16.bf16.f32 "
        "{%0,%1,%2,%3},{%4,%5,%6,%7},{%8,%9},{%0,%1,%2,%3};"
        : "+f"(c[0]), "+f"(c[1]), "+f"(c[2]), "+f"(c[3])
        : "r"(a[0]), "r"(a[1]), "r"(a[2]), "r"(a[3]), "r"(b[0]), "r"(b[1]));
}
// pack (f0,f1) -> bf16x2 {lo=f0, hi=f1}; residuals likewise
__device__ __forceinline__ void cvt_hi_lo(float f0, float f1, uint32_t& h, uint32_t& l) {
    asm("cvt.rn.bf16x2.f32 %0, %1, %2;" : "=r"(h) : "f"(f1), "f"(f0));
    float r0 = f0 - __uint_as_float(h << 16);
    float r1 = f1 - __uint_as_float(h & 0xFFFF0000u);
    asm("cvt.rn.bf16x2.f32 %0, %1, %2;" : "=r"(l) : "f"(r1), "f"(r0));
}

__global__ __launch_bounds__(256, 1) void swin_hmma(
    const float* __restrict__ x,
    const float* __restrict__ W,
    const float* __restrict__ bias,
    float* __restrict__ out)
{
    extern __shared__ char sm[];
    const uint32_t sbase = smem_u32(sm);

    const int tid = threadIdx.x;
    const int wid = tid >> 5;
    const int lid = tid & 31;
    const int wm  = wid >> 2;          // 0..1 : m offset wm*64
    const int wn  = wid & 3;           // 0..3 : n offset wn*32

    const int o0 = blockIdx.x * 128;
    const int p0 = blockIdx.y * 128;
    const int bg = blockIdx.z;
    const int b32 = (bg >> 1) * 32;
    const int g32 = (bg & 1) * 32;

    // ---- loader thread mapping ----
    const int cA = tid >> 3;           // 0..31 : k row of A chunk (== channel c)
    const int mq = tid & 7;            // A: float4 at m = 4*(mq + 8u)
    const int oB = tid >> 3;           // B: o = oB + 32u
    const int kq = tid & 7;            // B: float4 at k = 4*kq

    // ---- ldmatrix per-lane address parts ----
    const int li  = lid & 7;
    const int gA  = (lid >> 4) & 1;    // +8 on row (k) for groups 2,3
    const int gB  = (lid >> 3) & 1;    // +8 on col for groups 1,3
    // A (trans, [k][m]): off = (k0 + li + 8*gA)*272 + (m0 + 8*gB)*2
    const uint32_t a_lane = (uint32_t)((li + 8 * gA) * A_STRIDE + (wm * 64 + 8 * gB) * 2);
    // B (non-trans, [o][k]): off = (n0 + li + 8*gA)*80 + (k0 + 8*gB)*2
    const uint32_t b_lane = (uint32_t)((wn * 32 + li + 8 * gA) * B_STRIDE + (8 * gB) * 2);

    float acc[4][4][4];
    #pragma unroll
    for (int i = 0; i < 4; i++)
        #pragma unroll
        for (int j = 0; j < 4; j++)
            #pragma unroll
            for (int r = 0; r < 4; r++) acc[i][j][r] = 0.f;

    float4 pa[4], pb[4];

    // prefetch chunk 0
    {
        const int t = (g32 + 0 + 48) & 63;
        const float* ap = x + ((size_t)(b32 + cA) * 64 + t) * PDIM + p0;
        #pragma unroll
        for (int u = 0; u < 4; u++) pa[u] = *(const float4*)(ap + 4 * (mq + 8 * u));
        #pragma unroll
        for (int u = 0; u < 4; u++)
            pb[u] = *(const float4*)(W + (size_t)(o0 + oB + 32 * u) * 1024 + 4 * kq);
    }

    #pragma unroll 1
    for (int i = 0; i < NCH; i++) {
        char* stg = sm + (i & 1) * STAGE;
        // ---- convert + STS current chunk ----
        {
            char* Ah = stg + OFF_AHI + cA * A_STRIDE;
            char* Al = stg + OFF_ALO + cA * A_STRIDE;
            #pragma unroll
            for (int u = 0; u < 4; u++) {
                uint32_t h0, l0, h1, l1;
                cvt_hi_lo(pa[u].x, pa[u].y, h0, l0);
                cvt_hi_lo(pa[u].z, pa[u].w, h1, l1);
                const int moff = 8 * (mq + 8 * u);       // bytes: m*2
                *(uint2*)(Ah + moff) = make_uint2(h0, h1);
                *(uint2*)(Al + moff) = make_uint2(l0, l1);
            }
            #pragma unroll
            for (int u = 0; u < 4; u++) {
                uint32_t h0, l0, h1, l1;
                cvt_hi_lo(pb[u].x, pb[u].y, h0, l0);
                cvt_hi_lo(pb[u].z, pb[u].w, h1, l1);
                char* Bh = stg + OFF_BHI + (oB + 32 * u) * B_STRIDE + kq * 8;
                char* Bl = stg + OFF_BLO + (oB + 32 * u) * B_STRIDE + kq * 8;
                *(uint2*)Bh = make_uint2(h0, h1);
                *(uint2*)Bl = make_uint2(l0, l1);
            }
        }
        // ---- prefetch next chunk (latency hidden by barrier + MMA) ----
        if (i + 1 < NCH) {
            const int t = (g32 + (i + 1) + 48) & 63;
            const float* ap = x + ((size_t)(b32 + cA) * 64 + t) * PDIM + p0;
            #pragma unroll
            for (int u = 0; u < 4; u++) pa[u] = *(const float4*)(ap + 4 * (mq + 8 * u));
            const float* wp = W + (i + 1) * 32 + 4 * kq;
            #pragma unroll
            for (int u = 0; u < 4; u++)
                pb[u] = *(const float4*)(wp + (size_t)(o0 + oB + 32 * u) * 1024);
        }
        __syncthreads();

        // ---- compute: 2 x k16, 3 passes ----
        const uint32_t ahi = sbase + (i & 1) * STAGE + OFF_AHI + a_lane;
        const uint32_t alo = sbase + (i & 1) * STAGE + OFF_ALO + a_lane;
        const uint32_t bhi = sbase + (i & 1) * STAGE + OFF_BHI + b_lane;
        const uint32_t blo = sbase + (i & 1) * STAGE + OFF_BLO + b_lane;
        #pragma unroll
        for (int ks = 0; ks < 2; ks++) {
            uint32_t Ah[4][4], Al[4][4], Bh[2][4], Bl[2][4];
            #pragma unroll
            for (int bm = 0; bm < 4; bm++) {
                ldsm_x4_t(Ah[bm], ahi + ks * 16 * A_STRIDE + bm * 32);
                ldsm_x4_t(Al[bm], alo + ks * 16 * A_STRIDE + bm * 32);
            }
            #pragma unroll
            for (int bp = 0; bp < 2; bp++) {
                ldsm_x4(Bh[bp], bhi + bp * 16 * B_STRIDE + ks * 32);
                ldsm_x4(Bl[bp], blo + bp * 16 * B_STRIDE + ks * 32);
            }
            #pragma unroll
            for (int bm = 0; bm < 4; bm++)
                #pragma unroll
                for (int bn = 0; bn < 4; bn++)
                    mma_bf16(acc[bm][bn], Ah[bm], &Bh[bn >> 1][(bn & 1) * 2]);
            #pragma unroll
            for (int bm = 0; bm < 4; bm++)
                #pragma unroll
                for (int bn = 0; bn < 4; bn++)
                    mma_bf16(acc[bm][bn], Al[bm], &Bh[bn >> 1][(bn & 1) * 2]);
            #pragma unroll
            for (int bm = 0; bm < 4; bm++)
                #pragma unroll
                for (int bn = 0; bn < 4; bn++)
                    mma_bf16(acc[bm][bn], Ah[bm], &Bl[bn >> 1][(bn & 1) * 2]);
        }
        __syncthreads();
    }

    // ---- epilogue: scatter with bias ----
    const int row = lid >> 2;
    const int col2 = (lid & 3) * 2;
    #pragma unroll
    for (int bm = 0; bm < 4; bm++) {
        #pragma unroll
        for (int bn = 0; bn < 4; bn++) {
            #pragma unroll
            for (int rh = 0; rh < 2; rh++) {
                const int m = wm * 64 + bm * 16 + row + rh * 8;
                #pragma unroll
                for (int cc = 0; cc < 2; cc++) {
                    const int o = o0 + wn * 32 + bn * 8 + col2 + cc;
                    const int t = (g32 + (o >> 5) + 48) & 63;
                    const size_t idx = ((size_t)(b32 + (o & 31)) * 64 + t) * PDIM + p0 + m;
                    out[idx] = acc[bm][bn][rh * 2 + cc] + __ldg(&bias[o]);
                }
            }
        }
    }
}

extern "C" void kernel_launch(void* const* d_in, const int* in_sizes, int n_in,
                              void* d_out, int out_size)
{
    const float* x    = (const float*)d_in[0];
    const float* W    = (const float*)d_in[1];
    const float* bias = (const float*)d_in[2];
    float* out        = (float*)d_out;

    cudaFuncSetAttribute(swin_hmma, cudaFuncAttributeMaxDynamicSharedMemorySize, DYN_SMEM);
    dim3 grid(1024 / 128 /*8*/, PDIM / 128 /*108*/, 4 /*b*2+g*/);
    swin_hmma<<<grid, 256, DYN_SMEM>>>(x, W, bias, out);
}

// round 12
// speedup vs baseline: 4.0182x; 2.0811x over previous
#include <cuda_runtime.h>
#include <cuda_fp16.h>
#include <cstdint>

// Y[m,o] = sum_k A[m,k]*W[o,k] + bias[o]
// m=(b,g,p), k=s*32+c gathered from x at t=(g*32+s+48)&63; same map on output o.
// Precompute: xh=fp16(x), xl=fp16(x-xh), wh=fp16(W).
// 2-pass split: Y ~= xh*wh + xl*wh  (dropped A*Wl term ~1.4e-4 rel, gate is 1e-3)

#define PDIM 13824
#define NCH  32            // K chunks of 32 (s == chunk index)
#define NSTAGE 4
// smem per stage (bytes)
#define A_STRIDE 272       // [k=32][m=128] fp16, 256B rows padded to 272
#define B_STRIDE 80        // [o=128][k=32] fp16, 64B rows padded to 80
#define OFF_AHI 0
#define OFF_ALO 8704       // 32*272
#define OFF_BHI 17408
#define STAGE   27648      // + 128*80
#define DYN_SMEM (NSTAGE*STAGE)

// fp16 hi/lo of x, fp16 of W (scratch via __device__ globals)
__device__ __align__(16) __half xh_g[56623104];
__device__ __align__(16) __half xl_g[56623104];
__device__ __align__(16) __half wh_g[1048576];

__device__ __forceinline__ uint32_t smem_u32(const void* p) {
    uint32_t a;
    asm("{ .reg .u64 t; cvta.to.shared.u64 t, %1; cvt.u32.u64 %0, t; }" : "=r"(a) : "l"(p));
    return a;
}
__device__ __forceinline__ void ldsm_x4_t(uint32_t* r, uint32_t a) {
    asm volatile("ldmatrix.sync.aligned.m8n8.x4.trans.shared.b16 {%0,%1,%2,%3},[%4];"
        : "=r"(r[0]), "=r"(r[1]), "=r"(r[2]), "=r"(r[3]) : "r"(a));
}
__device__ __forceinline__ void ldsm_x4(uint32_t* r, uint32_t a) {
    asm volatile("ldmatrix.sync.aligned.m8n8.x4.shared.b16 {%0,%1,%2,%3},[%4];"
        : "=r"(r[0]), "=r"(r[1]), "=r"(r[2]), "=r"(r[3]) : "r"(a));
}
__device__ __forceinline__ void mma_f16(float* c, const uint32_t* a, const uint32_t* b) {
    asm volatile("mma.sync.aligned.m16n8k16.row.col.f32.f16.f16.f32 "
        "{%0,%1,%2,%3},{%4,%5,%6,%7},{%8,%9},{%0,%1,%2,%3};"
        : "+f"(c[0]), "+f"(c[1]), "+f"(c[2]), "+f"(c[3])
        : "r"(a[0]), "r"(a[1]), "r"(a[2]), "r"(a[3]), "r"(b[0]), "r"(b[1]));
}
#define CP16(dst, src) asm volatile("cp.async.cg.shared.global [%0], [%1], 16;" :: "r"(dst), "l"(src))
#define CP_COMMIT()    asm volatile("cp.async.commit_group;" ::: "memory")
#define CP_WAIT(n)     asm volatile("cp.async.wait_group %0;" :: "n"(n) : "memory")

// ---------------- precompute kernels ----------------
__global__ __launch_bounds__(256) void prep_x(const float4* __restrict__ x4) {
    const size_t i = (size_t)blockIdx.x * 256 + threadIdx.x;   // 14,155,776 exact
    const float4 v = x4[i];
    const __half h0 = __float2half_rn(v.x), h1 = __float2half_rn(v.y);
    const __half h2 = __float2half_rn(v.z), h3 = __float2half_rn(v.w);
    const __half l0 = __float2half_rn(v.x - __half2float(h0));
    const __half l1 = __float2half_rn(v.y - __half2float(h1));
    const __half l2 = __float2half_rn(v.z - __half2float(h2));
    const __half l3 = __float2half_rn(v.w - __half2float(h3));
    __half2* xh2 = (__half2*)xh_g;
    __half2* xl2 = (__half2*)xl_g;
    xh2[2 * i]     = __halves2half2(h0, h1);
    xh2[2 * i + 1] = __halves2half2(h2, h3);
    xl2[2 * i]     = __halves2half2(l0, l1);
    xl2[2 * i + 1] = __halves2half2(l2, l3);
}
__global__ __launch_bounds__(256) void prep_w(const float4* __restrict__ w4) {
    const size_t i = (size_t)blockIdx.x * 256 + threadIdx.x;   // 262,144 exact
    const float4 v = w4[i];
    __half2* wh2 = (__half2*)wh_g;
    wh2[2 * i]     = __halves2half2(__float2half_rn(v.x), __float2half_rn(v.y));
    wh2[2 * i + 1] = __halves2half2(__float2half_rn(v.z), __float2half_rn(v.w));
}

// ---------------- main GEMM ----------------
__global__ __launch_bounds__(256, 1) void swin_hmma2(
    const float* __restrict__ bias,
    float* __restrict__ out)
{
    extern __shared__ char sm[];
    const uint32_t sbase = smem_u32(sm);

    const int tid = threadIdx.x;
    const int wid = tid >> 5;
    const int lid = tid & 31;
    const int wm  = wid >> 2;          // 0..1 : m offset wm*64
    const int wn  = wid & 3;           // 0..3 : n offset wn*32

    const int o0 = blockIdx.x * 128;
    const int p0 = blockIdx.y * 128;
    const int bg = blockIdx.z;
    const int b32 = (bg >> 1) * 32;
    const int g32 = (bg & 1) * 32;

    // loader mapping (2 iters each for A-hi/A-lo, 2 for B)
    const int aRow = tid >> 4;         // +16 per iter : k row (channel c) halves-pair base
    const int aU   = tid & 15;         // 16B unit along m
    const int bRow = tid >> 2;         // +64 per iter : o row
    const int bU   = tid & 3;          // 16B unit along k

    // ldmatrix lane addressing
    const int li = lid & 7;
    const int gA = (lid >> 4) & 1;
    const int gB = (lid >> 3) & 1;
    const uint32_t a_lane = (uint32_t)((li + 8 * gA) * A_STRIDE + (wm * 64 + 8 * gB) * 2);
    const uint32_t b_lane = (uint32_t)((wn * 32 + li + 8 * gA) * B_STRIDE + (8 * gB) * 2);

    float acc[4][4][4];
    #pragma unroll
    for (int i = 0; i < 4; i++)
        #pragma unroll
        for (int j = 0; j < 4; j++)
            #pragma unroll
            for (int r = 0; r < 4; r++) acc[i][j][r] = 0.f;

    // -------- chunk loader (all 256 threads, 6 cp.async each) --------
    auto load_chunk = [&](int i) {
        const uint32_t stg = sbase + (uint32_t)(i & (NSTAGE - 1)) * STAGE;
        const int t = (g32 + i + 48) & 63;
        #pragma unroll
        for (int w = 0; w < 2; w++) {
            const int row = aRow + 16 * w;
            const size_t src = ((size_t)(b32 + row) * 64 + t) * PDIM + p0 + aU * 8;
            const uint32_t dst = stg + row * A_STRIDE + aU * 16;
            CP16(dst + OFF_AHI, xh_g + src);
            CP16(dst + OFF_ALO, xl_g + src);
        }
        #pragma unroll
        for (int w = 0; w < 2; w++) {
            const int row = bRow + 64 * w;
            CP16(stg + OFF_BHI + row * B_STRIDE + bU * 16,
                 wh_g + (size_t)(o0 + row) * 1024 + i * 32 + bU * 8);
        }
    };

    // preload stages 0..NSTAGE-2
    #pragma unroll
    for (int i = 0; i < NSTAGE - 1; i++) { load_chunk(i); CP_COMMIT(); }

    #pragma unroll 1
    for (int i = 0; i < NCH; i++) {
        if (i + NSTAGE - 1 < NCH) load_chunk(i + NSTAGE - 1);
        CP_COMMIT();
        CP_WAIT(NSTAGE - 2);
        __syncthreads();

        const uint32_t stg = sbase + (uint32_t)(i & (NSTAGE - 1)) * STAGE;
        const uint32_t ahi = stg + OFF_AHI + a_lane;
        const uint32_t alo = stg + OFF_ALO + a_lane;
        const uint32_t bhi = stg + OFF_BHI + b_lane;
        #pragma unroll
        for (int ks = 0; ks < 2; ks++) {
            uint32_t Ah[4][4], Al[4][4], Bh[2][4];
            #pragma unroll
            for (int bm = 0; bm < 4; bm++) {
                ldsm_x4_t(Ah[bm], ahi + ks * 16 * A_STRIDE + bm * 32);
                ldsm_x4_t(Al[bm], alo + ks * 16 * A_STRIDE + bm * 32);
            }
            #pragma unroll
            for (int bp = 0; bp < 2; bp++)
                ldsm_x4(Bh[bp], bhi + bp * 16 * B_STRIDE + ks * 32);
            #pragma unroll
            for (int bm = 0; bm < 4; bm++)
                #pragma unroll
                for (int bn = 0; bn < 4; bn++)
                    mma_f16(acc[bm][bn], Ah[bm], &Bh[bn >> 1][(bn & 1) * 2]);
            #pragma unroll
            for (int bm = 0; bm < 4; bm++)
                #pragma unroll
                for (int bn = 0; bn < 4; bn++)
                    mma_f16(acc[bm][bn], Al[bm], &Bh[bn >> 1][(bn & 1) * 2]);
        }
        __syncthreads();
    }

    // -------- epilogue: scatter with bias --------
    const int row = lid >> 2;
    const int col2 = (lid & 3) * 2;
    #pragma unroll
    for (int bm = 0; bm < 4; bm++) {
        #pragma unroll
        for (int bn = 0; bn < 4; bn++) {
            #pragma unroll
            for (int rh = 0; rh < 2; rh++) {
                const int m = wm * 64 + bm * 16 + row + rh * 8;
                #pragma unroll
                for (int cc = 0; cc < 2; cc++) {
                    const int o = o0 + wn * 32 + bn * 8 + col2 + cc;
                    const int t = (g32 + (o >> 5) + 48) & 63;
                    const size_t idx = ((size_t)(b32 + (o & 31)) * 64 + t) * PDIM + p0 + m;
                    out[idx] = acc[bm][bn][rh * 2 + cc] + __ldg(&bias[o]);
                }
            }
        }
    }
}

extern "C" void kernel_launch(void* const* d_in, const int* in_sizes, int n_in,
                              void* d_out, int out_size)
{
    const float* x    = (const float*)d_in[0];
    const float* W    = (const float*)d_in[1];
    const float* bias = (const float*)d_in[2];
    float* out        = (float*)d_out;

    prep_x<<<55296, 256>>>((const float4*)x);   // 14,155,776 float4s
    prep_w<<<1024, 256>>>((const float4*)W);    // 262,144 float4s

    cudaFuncSetAttribute(swin_hmma2, cudaFuncAttributeMaxDynamicSharedMemorySize, DYN_SMEM);
    dim3 grid(1024 / 128 /*8*/, PDIM / 128 /*108*/, 4 /*b*2+g*/);
    swin_hmma2<<<grid, 256, DYN_SMEM>>>(bias, out);
}